// round 6
// baseline (speedup 1.0000x reference)
#include <cuda_runtime.h>
#include <cstdint>
#include <math.h>

#define B_  2
#define T_  2048
#define D_  1024
#define H_  16
#define DH_ 64
#define BT_ (B_*T_)

// ---------------- scratch (static device allocations; no cudaMalloc) -------
__device__ float g_qkv[(size_t)BT_ * 3 * D_];   // [B,T,3072]
__device__ float g_w1p[(size_t)BT_ * 64];       // x_prev @ w1_write^T  [B,T,H,4]
__device__ float g_w2p[(size_t)BT_ * 64];
__device__ float g_r1p[(size_t)BT_ * 64];
__device__ float g_r2p[(size_t)BT_ * 64];
__device__ float g_rl [(size_t)BT_ * H_ * 6];   // normalized read lines
__device__ float g_jw [(size_t)BT_ * H_ * 6];   // J6-transformed normalized write lines
__device__ float g_ctx[(size_t)BT_ * D_];       // attention context [B,T,D]

// ---------------- generic tiled SGEMM: C[M,N] = A[M,K] @ B[N,K]^T (+bias) ---
// 64x64 block tile, K-step 16, 256 threads, 4x4 micro-tile with interleaved
// column mapping (col = tx + j*16) for conflict-free LDS.
template <bool HAS_BIAS>
__global__ void sgemm_nt(const float* __restrict__ A, int lda,
                         const float* __restrict__ Bm,       // [N,K] row-major
                         const float* __restrict__ bias,
                         float* __restrict__ C, int ldc,
                         int M, int N, int K)
{
    __shared__ float As[16][65];
    __shared__ float Bs[16][65];

    const int bm = blockIdx.y * 64;
    const int bn = blockIdx.x * 64;
    const int tid = threadIdx.x;
    const int tx = tid & 15;
    const int ty = tid >> 4;

    float acc[4][4] = {};

    const int lm  = tid >> 2;        // 0..63
    const int lk  = (tid & 3) * 4;   // 0,4,8,12

    for (int k0 = 0; k0 < K; k0 += 16) {
        // load A tile (64 x 16)
        {
            const int row = bm + lm;
            float4 v = make_float4(0.f, 0.f, 0.f, 0.f);
            if (row < M)
                v = *reinterpret_cast<const float4*>(A + (size_t)row * lda + k0 + lk);
            As[lk + 0][lm] = v.x; As[lk + 1][lm] = v.y;
            As[lk + 2][lm] = v.z; As[lk + 3][lm] = v.w;
        }
        // load B tile (64 x 16)
        {
            const int col = bn + lm;
            float4 v = make_float4(0.f, 0.f, 0.f, 0.f);
            if (col < N)
                v = *reinterpret_cast<const float4*>(Bm + (size_t)col * K + k0 + lk);
            Bs[lk + 0][lm] = v.x; Bs[lk + 1][lm] = v.y;
            Bs[lk + 2][lm] = v.z; Bs[lk + 3][lm] = v.w;
        }
        __syncthreads();

        #pragma unroll
        for (int kk = 0; kk < 16; kk++) {
            float a[4], b[4];
            #pragma unroll
            for (int i = 0; i < 4; i++) a[i] = As[kk][ty + i * 16];
            #pragma unroll
            for (int j = 0; j < 4; j++) b[j] = Bs[kk][tx + j * 16];
            #pragma unroll
            for (int i = 0; i < 4; i++)
                #pragma unroll
                for (int j = 0; j < 4; j++)
                    acc[i][j] += a[i] * b[j];
        }
        __syncthreads();
    }

    #pragma unroll
    for (int i = 0; i < 4; i++) {
        const int row = bm + ty + i * 16;
        if (row >= M) continue;
        #pragma unroll
        for (int j = 0; j < 4; j++) {
            const int col = bn + tx + j * 16;
            if (col >= N) continue;
            float v = acc[i][j];
            if (HAS_BIAS) v += bias[col];
            C[(size_t)row * ldc + col] = v;
        }
    }
}

// ---------------- zero row t=0 of w1p for each batch -----------------------
__global__ void w1p_zero_rows(float* __restrict__ w1p)
{
    const int i = threadIdx.x;           // 128 threads
    const int b = i >> 6;
    const int c = i & 63;
    w1p[(size_t)(b * T_) * 64 + c] = 0.f;
}

// ---------------- exterior products -> normalized lines --------------------
__device__ __forceinline__ void exterior6(const float* a, const float* b, float* L)
{
    L[0] = a[0] * b[1] - a[1] * b[0];
    L[1] = a[0] * b[2] - a[2] * b[0];
    L[2] = a[0] * b[3] - a[3] * b[0];
    L[3] = a[1] * b[2] - a[2] * b[1];
    L[4] = a[1] * b[3] - a[3] * b[1];
    L[5] = a[2] * b[3] - a[3] * b[2];
}

__global__ void lines_kernel(const float* __restrict__ w1p, const float* __restrict__ w2p,
                             const float* __restrict__ r1p, const float* __restrict__ r2p,
                             float* __restrict__ rl, float* __restrict__ jw)
{
    const int i = blockIdx.x * blockDim.x + threadIdx.x;   // over BT*H
    if (i >= BT_ * H_) return;
    const int i4 = i * 4;
    const int i6 = i * 6;

    // write line -> apply J6 -> jw
    {
        float a[4], b[4], L[6];
        #pragma unroll
        for (int p = 0; p < 4; p++) { a[p] = w1p[i4 + p]; b[p] = w2p[i4 + p]; }
        exterior6(a, b, L);
        float ss = 0.f;
        #pragma unroll
        for (int p = 0; p < 6; p++) ss += L[p] * L[p];
        const float inv = 1.f / fmaxf(sqrtf(ss), 1e-12f);
        jw[i6 + 0] =  L[5] * inv;
        jw[i6 + 1] = -L[4] * inv;
        jw[i6 + 2] =  L[3] * inv;
        jw[i6 + 3] =  L[2] * inv;
        jw[i6 + 4] = -L[1] * inv;
        jw[i6 + 5] =  L[0] * inv;
    }
    // read line -> rl
    {
        float a[4], b[4], L[6];
        #pragma unroll
        for (int p = 0; p < 4; p++) { a[p] = r1p[i4 + p]; b[p] = r2p[i4 + p]; }
        exterior6(a, b, L);
        float ss = 0.f;
        #pragma unroll
        for (int p = 0; p < 6; p++) ss += L[p] * L[p];
        const float inv = 1.f / fmaxf(sqrtf(ss), 1e-12f);
        #pragma unroll
        for (int p = 0; p < 6; p++) rl[i6 + p] = L[p] * inv;
    }
}

// ---------------- fused causal attention with incidence bias ----------------
// grid: (B*H, T/64). block: 256 threads. flash-style online softmax.
#define PITCH 65
#define ATTN_SMEM_BYTES ((4 * 64 * PITCH + 2 * 64 * 6) * 4)

__global__ void attn_kernel(const float* __restrict__ qkv,
                            const float* __restrict__ rl,
                            const float* __restrict__ jw,
                            const float* __restrict__ decay_logits,
                            const float* __restrict__ bias_scale,
                            float* __restrict__ ctx)
{
    extern __shared__ float sm[];
    float* Qs  = sm;                       // 64*PITCH
    float* Ks  = Qs  + 64 * PITCH;
    float* Vs  = Ks  + 64 * PITCH;
    float* Ps  = Vs  + 64 * PITCH;
    float* rls = Ps  + 64 * PITCH;         // 64*6
    float* jws = rls + 64 * 6;             // 64*6

    const int bh = blockIdx.x;
    const int b  = bh >> 4;
    const int h  = bh & 15;
    const int qt = blockIdx.y;
    const int q0 = qt * 64;

    const int tid = threadIdx.x;
    const int tx  = tid & 15;
    const int ty  = tid >> 4;

    const float scale = 0.125f;            // dh^-0.5, dh=64
    const float dlv   = decay_logits[h];
    const float decay = 1.f / (1.f + __expf(-dlv));
    const float ldec  = __logf(decay);
    const float bs    = bias_scale[h];

    const float* qbase  = qkv + (size_t)(b * T_) * 3072 + h * 64;
    const float* rlbase = rl  + ((size_t)(b * T_) * H_ + h) * 6;
    const float* jwbase = jw  + ((size_t)(b * T_) * H_ + h) * 6;

    // load Q tile [64 x 64] and rl tile [64 x 6]
    #pragma unroll
    for (int v = 0; v < 4; v++) {
        const int lin = tid + v * 256;
        const int r = lin >> 4;
        const int c = (lin & 15) * 4;
        const float4 x4 = *reinterpret_cast<const float4*>(
            qbase + (size_t)(q0 + r) * 3072 + c);
        Qs[r * PITCH + c + 0] = x4.x; Qs[r * PITCH + c + 1] = x4.y;
        Qs[r * PITCH + c + 2] = x4.z; Qs[r * PITCH + c + 3] = x4.w;
    }
    for (int idx = tid; idx < 384; idx += 256) {
        const int r = idx / 6, p = idx % 6;
        rls[r * 6 + p] = rlbase[(size_t)(q0 + r) * (H_ * 6) + p];
    }

    float m[4], l[4], o[4][4];
    #pragma unroll
    for (int i = 0; i < 4; i++) {
        m[i] = -1e30f; l[i] = 0.f;
        #pragma unroll
        for (int j = 0; j < 4; j++) o[i][j] = 0.f;
    }

    for (int kt = 0; kt <= qt; kt++) {
        const int k0 = kt * 64;
        __syncthreads();   // previous iteration's Vs/Ps reads done

        // load K, V tiles [64 x 64], jw tile [64 x 6]
        #pragma unroll
        for (int v = 0; v < 4; v++) {
            const int lin = tid + v * 256;
            const int r = lin >> 4;
            const int c = (lin & 15) * 4;
            const float* kp = qkv + (size_t)(b * T_ + k0 + r) * 3072 + 1024 + h * 64 + c;
            const float4 k4 = *reinterpret_cast<const float4*>(kp);
            const float4 v4 = *reinterpret_cast<const float4*>(kp + 1024);
            Ks[r * PITCH + c + 0] = k4.x; Ks[r * PITCH + c + 1] = k4.y;
            Ks[r * PITCH + c + 2] = k4.z; Ks[r * PITCH + c + 3] = k4.w;
            Vs[r * PITCH + c + 0] = v4.x; Vs[r * PITCH + c + 1] = v4.y;
            Vs[r * PITCH + c + 2] = v4.z; Vs[r * PITCH + c + 3] = v4.w;
        }
        for (int idx = tid; idx < 384; idx += 256) {
            const int r = idx / 6, p = idx % 6;
            jws[r * 6 + p] = jwbase[(size_t)(k0 + r) * (H_ * 6) + p];
        }
        __syncthreads();

        // S = Q K^T
        float s[4][4] = {};
        #pragma unroll 8
        for (int e = 0; e < 64; e++) {
            float a[4], bb[4];
            #pragma unroll
            for (int i = 0; i < 4; i++) a[i]  = Qs[(ty + i * 16) * PITCH + e];
            #pragma unroll
            for (int j = 0; j < 4; j++) bb[j] = Ks[(tx + j * 16) * PITCH + e];
            #pragma unroll
            for (int i = 0; i < 4; i++)
                #pragma unroll
                for (int j = 0; j < 4; j++)
                    s[i][j] += a[i] * bb[j];
        }

        // scale + incidence bias + causal mask
        #pragma unroll
        for (int i = 0; i < 4; i++) {
            const int qr = ty + i * 16;
            const int qi = q0 + qr;
            #pragma unroll
            for (int j = 0; j < 4; j++) {
                const int kr = tx + j * 16;
                const int kg = k0 + kr;
                float sv = s[i][j] * scale;
                const int dq = qi - kg;
                if (dq < 0) {
                    sv = -1e30f;
                } else if (dq > 0) {
                    float inc = 0.f;
                    #pragma unroll
                    for (int p = 0; p < 6; p++)
                        inc += rls[qr * 6 + p] * jws[kr * 6 + p];
                    sv += inc * bs * __expf(ldec * (float)dq);
                }
                s[i][j] = sv;
            }
        }

        // online softmax (row spread over 16 lanes, width-16 shfl)
        #pragma unroll
        for (int i = 0; i < 4; i++) {
            float mx = fmaxf(fmaxf(s[i][0], s[i][1]), fmaxf(s[i][2], s[i][3]));
            #pragma unroll
            for (int off = 8; off >= 1; off >>= 1)
                mx = fmaxf(mx, __shfl_xor_sync(0xffffffffu, mx, off, 16));
            const float m_new = fmaxf(m[i], mx);
            const float alpha = __expf(m[i] - m_new);
            float psum = 0.f;
            #pragma unroll
            for (int j = 0; j < 4; j++) {
                const float p = __expf(s[i][j] - m_new);
                s[i][j] = p;
                psum += p;
            }
            #pragma unroll
            for (int off = 8; off >= 1; off >>= 1)
                psum += __shfl_xor_sync(0xffffffffu, psum, off, 16);
            l[i] = l[i] * alpha + psum;
            m[i] = m_new;
            #pragma unroll
            for (int j = 0; j < 4; j++) o[i][j] *= alpha;
        }

        // stage P
        #pragma unroll
        for (int i = 0; i < 4; i++)
            #pragma unroll
            for (int j = 0; j < 4; j++)
                Ps[(ty + i * 16) * PITCH + tx + j * 16] = s[i][j];
        __syncthreads();

        // O += P V
        #pragma unroll 8
        for (int kk = 0; kk < 64; kk++) {
            float p[4], vv[4];
            #pragma unroll
            for (int i = 0; i < 4; i++) p[i]  = Ps[(ty + i * 16) * PITCH + kk];
            #pragma unroll
            for (int j = 0; j < 4; j++) vv[j] = Vs[kk * PITCH + tx + j * 16];
            #pragma unroll
            for (int i = 0; i < 4; i++)
                #pragma unroll
                for (int j = 0; j < 4; j++)
                    o[i][j] += p[i] * vv[j];
        }
    }

    // epilogue: normalize, write ctx[b, q, h*64 + e]
    #pragma unroll
    for (int i = 0; i < 4; i++) {
        const float inv = 1.f / l[i];
        const int qi = q0 + ty + i * 16;
        #pragma unroll
        for (int j = 0; j < 4; j++) {
            const int e = tx + j * 16;
            ctx[(size_t)(b * T_ + qi) * D_ + h * 64 + e] = o[i][j] * inv;
        }
    }
}

// ---------------- launch ----------------------------------------------------
extern "C" void kernel_launch(void* const* d_in, const int* in_sizes, int n_in,
                              void* d_out, int out_size)
{
    const float* x      = (const float*)d_in[0];
    const float* w_qkv  = (const float*)d_in[1];
    const float* b_qkv  = (const float*)d_in[2];
    const float* w1w    = (const float*)d_in[3];
    const float* w2w    = (const float*)d_in[4];
    const float* w1r    = (const float*)d_in[5];
    const float* w2r    = (const float*)d_in[6];
    const float* w_out  = (const float*)d_in[7];
    const float* b_out  = (const float*)d_in[8];
    const float* dlg    = (const float*)d_in[9];
    const float* bsc    = (const float*)d_in[10];
    float* out = (float*)d_out;

    float *qkv, *w1p, *w2p, *r1p, *r2p, *rlp, *jwp, *ctx;
    cudaGetSymbolAddress((void**)&qkv, g_qkv);
    cudaGetSymbolAddress((void**)&w1p, g_w1p);
    cudaGetSymbolAddress((void**)&w2p, g_w2p);
    cudaGetSymbolAddress((void**)&r1p, g_r1p);
    cudaGetSymbolAddress((void**)&r2p, g_r2p);
    cudaGetSymbolAddress((void**)&rlp, g_rl);
    cudaGetSymbolAddress((void**)&jwp, g_jw);
    cudaGetSymbolAddress((void**)&ctx, g_ctx);

    const dim3 blk(256);

    // QKV projection: [4096,3072] = x @ w_qkv^T + b_qkv
    sgemm_nt<true><<<dim3(3072 / 64, BT_ / 64), blk>>>(
        x, D_, w_qkv, b_qkv, qkv, 3 * D_, BT_, 3 * D_, D_);

    // line projections (N = 64 each)
    sgemm_nt<false><<<dim3(1, BT_ / 64), blk>>>(x, D_, w2w, nullptr, w2p, 64, BT_, 64, D_);
    sgemm_nt<false><<<dim3(1, BT_ / 64), blk>>>(x, D_, w1r, nullptr, r1p, 64, BT_, 64, D_);
    sgemm_nt<false><<<dim3(1, BT_ / 64), blk>>>(x, D_, w2r, nullptr, r2p, 64, BT_, 64, D_);

    // w1p = x_prev @ w1_write^T : zero row t=0 per batch, shifted GEMM for the rest
    w1p_zero_rows<<<1, 128>>>(w1p);
    for (int b = 0; b < B_; b++) {
        sgemm_nt<false><<<dim3(1, (T_ - 1 + 63) / 64), blk>>>(
            x + (size_t)b * T_ * D_, D_, w1w, nullptr,
            w1p + ((size_t)(b * T_) + 1) * 64, 64, T_ - 1, 64, D_);
    }

    // exterior products -> rl, jw
    lines_kernel<<<(BT_ * H_ + 255) / 256, 256>>>(w1p, w2p, r1p, r2p, rlp, jwp);

    // fused biased causal attention
    cudaFuncSetAttribute(attn_kernel, cudaFuncAttributeMaxDynamicSharedMemorySize,
                         ATTN_SMEM_BYTES);
    attn_kernel<<<dim3(B_ * H_, T_ / 64), blk, ATTN_SMEM_BYTES>>>(
        qkv, rlp, jwp, dlg, bsc, ctx);

    // output projection
    sgemm_nt<true><<<dim3(D_ / 64, BT_ / 64), blk>>>(
        ctx, D_, w_out, b_out, out, D_, BT_, D_, D_);
}

// round 7
// speedup vs baseline: 1.4312x; 1.4312x over previous
#include <cuda_runtime.h>
#include <cstdint>
#include <math.h>

#define B_  2
#define T_  2048
#define D_  1024
#define H_  16
#define BT_ (B_*T_)

// ---------------- packed f32x2 helpers (Blackwell FFMA2 path) ---------------
#define FMA2(d, a, b)  asm("fma.rn.f32x2 %0, %1, %2, %0;" : "+l"(d) : "l"(a), "l"(b))
#define MUL2(d, a, b)  asm("mul.rn.f32x2 %0, %1, %2;"     : "=l"(d) : "l"(a), "l"(b))
#define PACK2(d, lo, hi) asm("mov.b64 %0, {%1, %2};" : "=l"(d) : "f"(lo), "f"(hi))
#define UNPK2(lo, hi, s) asm("mov.b64 {%0, %1}, %2;" : "=f"(lo), "=f"(hi) : "l"(s))
typedef unsigned long long u64;

// ---------------- scratch (static device allocations; no cudaMalloc) -------
__device__ float g_qkv [(size_t)BT_ * 3 * D_];   // [B,T,3072]
__device__ float g_wcat[(size_t)256 * D_];       // [w1w; w2w; w1r; w2r]
__device__ float g_proj[(size_t)BT_ * 256];      // x @ wcat^T
__device__ float g_rl  [(size_t)BT_ * H_ * 6];   // normalized read lines
__device__ float g_jw  [(size_t)BT_ * H_ * 6];   // J6 * normalized write lines
__device__ float g_ctx [(size_t)BT_ * D_];       // attention context

// =====================================================================
// 128x128 tile SGEMM, K-step 8, double-buffered, f32x2 accumulation.
// C[M,N] = A[M,K] @ B[N,K]^T (+bias). Requires M%128==0, N%128==0, K%8==0.
// 256 threads, 8x8 micro-tile (rows packed in f32x2 pairs).
// =====================================================================
template <bool HAS_BIAS>
__global__ void __launch_bounds__(256)
sgemm128(const float* __restrict__ A, const float* __restrict__ Bm,
         const float* __restrict__ bias, float* __restrict__ C,
         int M, int N, int K)
{
    __shared__ float As[2][8][136];
    __shared__ float Bs[2][8][136];

    const int bm = blockIdx.y * 128;
    const int bn = blockIdx.x * 128;
    const int tid = threadIdx.x;
    const int tx = tid & 15;        // 0..15 -> 8 cols each
    const int ty = tid >> 4;        // 0..15 -> 8 rows each

    const int lrow = tid >> 1;      // 0..127
    const int lkc  = (tid & 1) * 4; // 0 or 4

    const float* pA = A + (size_t)(bm + lrow) * K + lkc;
    const float* pB = Bm + (size_t)(bn + lrow) * K + lkc;

    u64 acc[4][8];
    #pragma unroll
    for (int i = 0; i < 4; i++)
        #pragma unroll
        for (int j = 0; j < 8; j++) acc[i][j] = 0ull;

    const int NT = K >> 3;

    float4 ra = *reinterpret_cast<const float4*>(pA);
    float4 rb = *reinterpret_cast<const float4*>(pB);
    {
        As[0][lkc + 0][lrow] = ra.x; As[0][lkc + 1][lrow] = ra.y;
        As[0][lkc + 2][lrow] = ra.z; As[0][lkc + 3][lrow] = ra.w;
        Bs[0][lkc + 0][lrow] = rb.x; Bs[0][lkc + 1][lrow] = rb.y;
        Bs[0][lkc + 2][lrow] = rb.z; Bs[0][lkc + 3][lrow] = rb.w;
    }
    __syncthreads();

    for (int it = 0; it < NT; it++) {
        const int cur = it & 1;
        const bool more = (it + 1 < NT);
        if (more) {
            ra = *reinterpret_cast<const float4*>(pA + (size_t)(it + 1) * 8);
            rb = *reinterpret_cast<const float4*>(pB + (size_t)(it + 1) * 8);
        }

        #pragma unroll
        for (int kk = 0; kk < 8; kk++) {
            const ulonglong2 A0 = *reinterpret_cast<const ulonglong2*>(&As[cur][kk][ty * 8]);
            const ulonglong2 A1 = *reinterpret_cast<const ulonglong2*>(&As[cur][kk][ty * 8 + 4]);
            const float4 b0 = *reinterpret_cast<const float4*>(&Bs[cur][kk][tx * 8]);
            const float4 b1 = *reinterpret_cast<const float4*>(&Bs[cur][kk][tx * 8 + 4]);
            u64 bd[8];
            PACK2(bd[0], b0.x, b0.x); PACK2(bd[1], b0.y, b0.y);
            PACK2(bd[2], b0.z, b0.z); PACK2(bd[3], b0.w, b0.w);
            PACK2(bd[4], b1.x, b1.x); PACK2(bd[5], b1.y, b1.y);
            PACK2(bd[6], b1.z, b1.z); PACK2(bd[7], b1.w, b1.w);
            u64 a2[4] = {A0.x, A0.y, A1.x, A1.y};
            #pragma unroll
            for (int pi = 0; pi < 4; pi++)
                #pragma unroll
                for (int j = 0; j < 8; j++)
                    FMA2(acc[pi][j], a2[pi], bd[j]);
        }

        if (more) {
            const int nxt = cur ^ 1;
            As[nxt][lkc + 0][lrow] = ra.x; As[nxt][lkc + 1][lrow] = ra.y;
            As[nxt][lkc + 2][lrow] = ra.z; As[nxt][lkc + 3][lrow] = ra.w;
            Bs[nxt][lkc + 0][lrow] = rb.x; Bs[nxt][lkc + 1][lrow] = rb.y;
            Bs[nxt][lkc + 2][lrow] = rb.z; Bs[nxt][lkc + 3][lrow] = rb.w;
        }
        __syncthreads();
    }

    // epilogue
    float bv[8] = {0.f,0.f,0.f,0.f,0.f,0.f,0.f,0.f};
    if (HAS_BIAS) {
        const float4 q0 = *reinterpret_cast<const float4*>(bias + bn + tx * 8);
        const float4 q1 = *reinterpret_cast<const float4*>(bias + bn + tx * 8 + 4);
        bv[0]=q0.x; bv[1]=q0.y; bv[2]=q0.z; bv[3]=q0.w;
        bv[4]=q1.x; bv[5]=q1.y; bv[6]=q1.z; bv[7]=q1.w;
    }
    #pragma unroll
    for (int pi = 0; pi < 4; pi++) {
        float lo[8], hi[8];
        #pragma unroll
        for (int j = 0; j < 8; j++) UNPK2(lo[j], hi[j], acc[pi][j]);
        const int r0 = bm + ty * 8 + pi * 2;
        float* c0 = C + (size_t)r0 * N + bn + tx * 8;
        float* c1 = c0 + N;
        float4 s0, s1;
        s0.x = lo[0]+bv[0]; s0.y = lo[1]+bv[1]; s0.z = lo[2]+bv[2]; s0.w = lo[3]+bv[3];
        s1.x = lo[4]+bv[4]; s1.y = lo[5]+bv[5]; s1.z = lo[6]+bv[6]; s1.w = lo[7]+bv[7];
        *reinterpret_cast<float4*>(c0)     = s0;
        *reinterpret_cast<float4*>(c0 + 4) = s1;
        s0.x = hi[0]+bv[0]; s0.y = hi[1]+bv[1]; s0.z = hi[2]+bv[2]; s0.w = hi[3]+bv[3];
        s1.x = hi[4]+bv[4]; s1.y = hi[5]+bv[5]; s1.z = hi[6]+bv[6]; s1.w = hi[7]+bv[7];
        *reinterpret_cast<float4*>(c1)     = s0;
        *reinterpret_cast<float4*>(c1 + 4) = s1;
    }
}

// =====================================================================
// 64x64 tile SGEMM (kept for the fused N=256 projection GEMM)
// =====================================================================
__global__ void sgemm64(const float* __restrict__ A, int lda,
                        const float* __restrict__ Bm,
                        float* __restrict__ C, int ldc,
                        int M, int N, int K)
{
    __shared__ float As[16][65];
    __shared__ float Bs[16][65];

    const int bm = blockIdx.y * 64;
    const int bn = blockIdx.x * 64;
    const int tid = threadIdx.x;
    const int tx = tid & 15;
    const int ty = tid >> 4;

    float acc[4][4] = {};
    const int lm = tid >> 2;
    const int lk = (tid & 3) * 4;

    for (int k0 = 0; k0 < K; k0 += 16) {
        {
            const float4 v = *reinterpret_cast<const float4*>(A + (size_t)(bm + lm) * lda + k0 + lk);
            As[lk + 0][lm] = v.x; As[lk + 1][lm] = v.y;
            As[lk + 2][lm] = v.z; As[lk + 3][lm] = v.w;
        }
        {
            const float4 v = *reinterpret_cast<const float4*>(Bm + (size_t)(bn + lm) * K + k0 + lk);
            Bs[lk + 0][lm] = v.x; Bs[lk + 1][lm] = v.y;
            Bs[lk + 2][lm] = v.z; Bs[lk + 3][lm] = v.w;
        }
        __syncthreads();
        #pragma unroll
        for (int kk = 0; kk < 16; kk++) {
            float a[4], b[4];
            #pragma unroll
            for (int i = 0; i < 4; i++) a[i] = As[kk][ty + i * 16];
            #pragma unroll
            for (int j = 0; j < 4; j++) b[j] = Bs[kk][tx + j * 16];
            #pragma unroll
            for (int i = 0; i < 4; i++)
                #pragma unroll
                for (int j = 0; j < 4; j++)
                    acc[i][j] += a[i] * b[j];
        }
        __syncthreads();
    }
    #pragma unroll
    for (int i = 0; i < 4; i++)
        #pragma unroll
        for (int j = 0; j < 4; j++)
            C[(size_t)(bm + ty + i * 16) * ldc + bn + tx + j * 16] = acc[i][j];
}

// ---------------- exterior products -> normalized lines --------------------
__device__ __forceinline__ void exterior6(const float* a, const float* b, float* L)
{
    L[0] = a[0] * b[1] - a[1] * b[0];
    L[1] = a[0] * b[2] - a[2] * b[0];
    L[2] = a[0] * b[3] - a[3] * b[0];
    L[3] = a[1] * b[2] - a[2] * b[1];
    L[4] = a[1] * b[3] - a[3] * b[1];
    L[5] = a[2] * b[3] - a[3] * b[2];
}

__global__ void lines_kernel(const float* __restrict__ proj,
                             float* __restrict__ rl, float* __restrict__ jw)
{
    const int i = blockIdx.x * blockDim.x + threadIdx.x;   // over BT*H
    if (i >= BT_ * H_) return;
    const int g = i >> 4;           // token index in [0, BT)
    const int h = i & 15;
    const int t = g & (T_ - 1);
    const int i6 = i * 6;
    const float* pr = proj + (size_t)g * 256;

    // write line (w1 from previous token) -> J6 -> jw
    {
        float a[4], b[4], L[6];
        #pragma unroll
        for (int p = 0; p < 4; p++) {
            a[p] = (t > 0) ? proj[(size_t)(g - 1) * 256 + h * 4 + p] : 0.f;
            b[p] = pr[64 + h * 4 + p];
        }
        exterior6(a, b, L);
        float ss = 0.f;
        #pragma unroll
        for (int p = 0; p < 6; p++) ss += L[p] * L[p];
        const float inv = 1.f / fmaxf(sqrtf(ss), 1e-12f);
        jw[i6 + 0] =  L[5] * inv;
        jw[i6 + 1] = -L[4] * inv;
        jw[i6 + 2] =  L[3] * inv;
        jw[i6 + 3] =  L[2] * inv;
        jw[i6 + 4] = -L[1] * inv;
        jw[i6 + 5] =  L[0] * inv;
    }
    // read line -> rl
    {
        float a[4], b[4], L[6];
        #pragma unroll
        for (int p = 0; p < 4; p++) {
            a[p] = pr[128 + h * 4 + p];
            b[p] = pr[192 + h * 4 + p];
        }
        exterior6(a, b, L);
        float ss = 0.f;
        #pragma unroll
        for (int p = 0; p < 6; p++) ss += L[p] * L[p];
        const float inv = 1.f / fmaxf(sqrtf(ss), 1e-12f);
        #pragma unroll
        for (int p = 0; p < 6; p++) rl[i6 + p] = L[p] * inv;
    }
}

// =====================================================================
// fused causal attention with incidence bias, f32x2 math.
// grid (B*H, T/64), 256 threads, 64x64 tiles, 4x4 micro (rows paired).
// =====================================================================
#define PITCH 68
#define ATTN_SMEM_BYTES ((4 * 64 * PITCH + 384 + 128) * 4)

__global__ void __launch_bounds__(256)
attn_kernel(const float* __restrict__ qkv,
            const float* __restrict__ rl,
            const float* __restrict__ jw,
            const float* __restrict__ decay_logits,
            const float* __restrict__ bias_scale,
            float* __restrict__ ctx)
{
    extern __shared__ float sm[];
    float* QT   = sm;                       // [e][qr]  64 x PITCH (transposed)
    float* KT   = QT + 64 * PITCH;          // [e][kr]
    float* Vs   = KT + 64 * PITCH;          // [kk][er] natural
    float* PT   = Vs + 64 * PITCH;          // [kk][qr] (transposed P)
    float* jws  = PT + 64 * PITCH;          // 64*6
    float* dpow = jws + 384;                // 127 entries: decay^(i-63)

    const int bh = blockIdx.x;
    const int b  = bh >> 4;
    const int h  = bh & 15;
    const int qt = blockIdx.y;
    const int q0 = qt * 64;

    const int tid = threadIdx.x;
    const int tx  = tid & 15;               // 4 cols each
    const int ty  = tid >> 4;               // 4 rows each

    const float scale = 0.125f;
    const float dlv   = decay_logits[h];
    const float decay = 1.f / (1.f + __expf(-dlv));
    const float ldec  = __logf(decay);
    const float bs    = bias_scale[h];

    const float* qbase  = qkv + (size_t)(b * T_) * 3072 + h * 64;
    const float* rlbase = rl  + ((size_t)(b * T_) * H_ + h) * 6;
    const float* jwbase = jw  + ((size_t)(b * T_) * H_ + h) * 6;

    if (tid < 127) dpow[tid] = __expf(ldec * (float)(tid - 63));

    // load Q tile transposed
    #pragma unroll
    for (int v = 0; v < 4; v++) {
        const int lin = tid + v * 256;
        const int r = lin >> 4;
        const int c = (lin & 15) * 4;
        const float4 x4 = *reinterpret_cast<const float4*>(qbase + (size_t)(q0 + r) * 3072 + c);
        QT[(c + 0) * PITCH + r] = x4.x; QT[(c + 1) * PITCH + r] = x4.y;
        QT[(c + 2) * PITCH + r] = x4.z; QT[(c + 3) * PITCH + r] = x4.w;
    }

    // read lines for this thread's 4 q-rows (fixed across kt) -> registers
    float rlr[4][6];
    #pragma unroll
    for (int i = 0; i < 4; i++) {
        const float* p = rlbase + (size_t)(q0 + ty * 4 + i) * (H_ * 6);
        #pragma unroll
        for (int pp = 0; pp < 6; pp++) rlr[i][pp] = p[pp];
    }

    float m[4], l[4];
    u64 o2[2][4];
    #pragma unroll
    for (int i = 0; i < 4; i++) { m[i] = -1e30f; l[i] = 0.f; }
    #pragma unroll
    for (int pi = 0; pi < 2; pi++)
        #pragma unroll
        for (int j = 0; j < 4; j++) o2[pi][j] = 0ull;

    for (int kt = 0; kt <= qt; kt++) {
        const int k0 = kt * 64;
        __syncthreads();

        // load K (transposed), V (natural), jw
        #pragma unroll
        for (int v = 0; v < 4; v++) {
            const int lin = tid + v * 256;
            const int r = lin >> 4;
            const int c = (lin & 15) * 4;
            const float* kp = qkv + (size_t)(b * T_ + k0 + r) * 3072 + 1024 + h * 64 + c;
            const float4 k4 = *reinterpret_cast<const float4*>(kp);
            const float4 v4 = *reinterpret_cast<const float4*>(kp + 1024);
            KT[(c + 0) * PITCH + r] = k4.x; KT[(c + 1) * PITCH + r] = k4.y;
            KT[(c + 2) * PITCH + r] = k4.z; KT[(c + 3) * PITCH + r] = k4.w;
            *reinterpret_cast<float4*>(&Vs[r * PITCH + c]) = v4;
        }
        for (int idx = tid; idx < 384; idx += 256) {
            const int r = idx / 6, p = idx % 6;
            jws[r * 6 + p] = jwbase[(size_t)(k0 + r) * (H_ * 6) + p];
        }
        __syncthreads();

        // S = Q K^T (rows paired in f32x2)
        u64 s2[2][4] = {{0ull,0ull,0ull,0ull},{0ull,0ull,0ull,0ull}};
        #pragma unroll 4
        for (int e = 0; e < 64; e++) {
            const ulonglong2 aq = *reinterpret_cast<const ulonglong2*>(&QT[e * PITCH + ty * 4]);
            const float4 kv = *reinterpret_cast<const float4*>(&KT[e * PITCH + tx * 4]);
            u64 kd[4];
            PACK2(kd[0], kv.x, kv.x); PACK2(kd[1], kv.y, kv.y);
            PACK2(kd[2], kv.z, kv.z); PACK2(kd[3], kv.w, kv.w);
            #pragma unroll
            for (int j = 0; j < 4; j++) {
                FMA2(s2[0][j], aq.x, kd[j]);
                FMA2(s2[1][j], aq.y, kd[j]);
            }
        }
        float s[4][4];
        #pragma unroll
        for (int j = 0; j < 4; j++) {
            UNPK2(s[0][j], s[1][j], s2[0][j]);
            UNPK2(s[2][j], s[3][j], s2[1][j]);
        }

        // scale + incidence bias + causal mask
        const float base = __expf(ldec * (float)(q0 - k0)) * bs;
        #pragma unroll
        for (int j = 0; j < 4; j++) {
            const int kr = tx * 4 + j;
            const int kg = k0 + kr;
            float jr[6];
            #pragma unroll
            for (int p = 0; p < 6; p++) jr[p] = jws[kr * 6 + p];
            #pragma unroll
            for (int i = 0; i < 4; i++) {
                const int qr = ty * 4 + i;
                const int dq = (q0 + qr) - kg;
                float sv = s[i][j] * scale;
                if (dq < 0) {
                    sv = -1e30f;
                } else if (dq > 0) {
                    float inc = 0.f;
                    #pragma unroll
                    for (int p = 0; p < 6; p++) inc += rlr[i][p] * jr[p];
                    sv += inc * base * dpow[qr - kr + 63];
                }
                s[i][j] = sv;
            }
        }

        // online softmax (row over 16 lanes sharing ty, width-16 shfl)
        float alpha[4];
        #pragma unroll
        for (int i = 0; i < 4; i++) {
            float mx = fmaxf(fmaxf(s[i][0], s[i][1]), fmaxf(s[i][2], s[i][3]));
            #pragma unroll
            for (int off = 8; off >= 1; off >>= 1)
                mx = fmaxf(mx, __shfl_xor_sync(0xffffffffu, mx, off, 16));
            const float m_new = fmaxf(m[i], mx);
            alpha[i] = __expf(m[i] - m_new);
            float psum = 0.f;
            #pragma unroll
            for (int j = 0; j < 4; j++) {
                const float p = __expf(s[i][j] - m_new);
                s[i][j] = p;
                psum += p;
            }
            #pragma unroll
            for (int off = 8; off >= 1; off >>= 1)
                psum += __shfl_xor_sync(0xffffffffu, psum, off, 16);
            l[i] = l[i] * alpha[i] + psum;
            m[i] = m_new;
        }
        {
            u64 al;
            PACK2(al, alpha[0], alpha[1]);
            #pragma unroll
            for (int j = 0; j < 4; j++) MUL2(o2[0][j], o2[0][j], al);
            PACK2(al, alpha[2], alpha[3]);
            #pragma unroll
            for (int j = 0; j < 4; j++) MUL2(o2[1][j], o2[1][j], al);
        }

        // stage P transposed: PT[kr][qr]
        #pragma unroll
        for (int i = 0; i < 4; i++)
            #pragma unroll
            for (int j = 0; j < 4; j++)
                PT[(tx * 4 + j) * PITCH + ty * 4 + i] = s[i][j];
        __syncthreads();

        // O += P V  (rows paired)
        #pragma unroll 4
        for (int kk = 0; kk < 64; kk++) {
            const ulonglong2 pp = *reinterpret_cast<const ulonglong2*>(&PT[kk * PITCH + ty * 4]);
            const float4 vv = *reinterpret_cast<const float4*>(&Vs[kk * PITCH + tx * 4]);
            u64 vd[4];
            PACK2(vd[0], vv.x, vv.x); PACK2(vd[1], vv.y, vv.y);
            PACK2(vd[2], vv.z, vv.z); PACK2(vd[3], vv.w, vv.w);
            #pragma unroll
            for (int j = 0; j < 4; j++) {
                FMA2(o2[0][j], pp.x, vd[j]);
                FMA2(o2[1][j], pp.y, vd[j]);
            }
        }
    }

    // epilogue: unpack, normalize, vectorized store
    float o[4][4];
    #pragma unroll
    for (int j = 0; j < 4; j++) {
        UNPK2(o[0][j], o[1][j], o2[0][j]);
        UNPK2(o[2][j], o[3][j], o2[1][j]);
    }
    #pragma unroll
    for (int i = 0; i < 4; i++) {
        const float inv = 1.f / l[i];
        const int qi = q0 + ty * 4 + i;
        float4 st;
        st.x = o[i][0] * inv; st.y = o[i][1] * inv;
        st.z = o[i][2] * inv; st.w = o[i][3] * inv;
        *reinterpret_cast<float4*>(ctx + (size_t)(b * T_ + qi) * D_ + h * 64 + tx * 4) = st;
    }
}

// ---------------- launch ----------------------------------------------------
extern "C" void kernel_launch(void* const* d_in, const int* in_sizes, int n_in,
                              void* d_out, int out_size)
{
    const float* x      = (const float*)d_in[0];
    const float* w_qkv  = (const float*)d_in[1];
    const float* b_qkv  = (const float*)d_in[2];
    const float* w1w    = (const float*)d_in[3];
    const float* w2w    = (const float*)d_in[4];
    const float* w1r    = (const float*)d_in[5];
    const float* w2r    = (const float*)d_in[6];
    const float* w_out  = (const float*)d_in[7];
    const float* b_out  = (const float*)d_in[8];
    const float* dlg    = (const float*)d_in[9];
    const float* bsc    = (const float*)d_in[10];
    float* out = (float*)d_out;

    float *qkv, *wcat, *proj, *rlp, *jwp, *ctx;
    cudaGetSymbolAddress((void**)&qkv,  g_qkv);
    cudaGetSymbolAddress((void**)&wcat, g_wcat);
    cudaGetSymbolAddress((void**)&proj, g_proj);
    cudaGetSymbolAddress((void**)&rlp,  g_rl);
    cudaGetSymbolAddress((void**)&jwp,  g_jw);
    cudaGetSymbolAddress((void**)&ctx,  g_ctx);

    const dim3 blk(256);
    const size_t wsz = (size_t)64 * D_ * sizeof(float);

    // concat projection weights: [w1w; w2w; w1r; w2r] -> [256, 1024]
    cudaMemcpyAsync(wcat,               w1w, wsz, cudaMemcpyDeviceToDevice);
    cudaMemcpyAsync(wcat + 64  * D_,    w2w, wsz, cudaMemcpyDeviceToDevice);
    cudaMemcpyAsync(wcat + 128 * D_,    w1r, wsz, cudaMemcpyDeviceToDevice);
    cudaMemcpyAsync(wcat + 192 * D_,    w2r, wsz, cudaMemcpyDeviceToDevice);

    // QKV projection (f32x2 SGEMM): [4096,3072]
    sgemm128<true><<<dim3(3072 / 128, BT_ / 128), blk>>>(
        x, w_qkv, b_qkv, qkv, BT_, 3 * D_, D_);

    // fused line projections: [4096,256] = x @ wcat^T
    sgemm64<<<dim3(256 / 64, BT_ / 64), blk>>>(
        x, D_, wcat, proj, 256, BT_, 256, D_);

    // exterior products -> rl, jw (x_prev shift handled inside)
    lines_kernel<<<(BT_ * H_ + 255) / 256, 256>>>(proj, rlp, jwp);

    // fused biased causal attention
    cudaFuncSetAttribute(attn_kernel, cudaFuncAttributeMaxDynamicSharedMemorySize,
                         ATTN_SMEM_BYTES);
    attn_kernel<<<dim3(B_ * H_, T_ / 64), blk, ATTN_SMEM_BYTES>>>(
        qkv, rlp, jwp, dlg, bsc, ctx);

    // output projection (f32x2 SGEMM): [4096,1024]
    sgemm128<true><<<dim3(D_ / 128, BT_ / 128), blk>>>(
        ctx, w_out, b_out, out, BT_, D_, D_);
}